// round 5
// baseline (speedup 1.0000x reference)
#include <cuda_runtime.h>
#include <math.h>

#define NMAX 50000
#define EMAX 1600000

// ---- static device scratch (no runtime allocation allowed) ----
__device__ int   g_cnt[NMAX];
__device__ int   g_off[NMAX + 1];
__device__ int   g_cur[NMAX];
__device__ float g_dinv[NMAX];
__device__ int   g_csrc[EMAX];
__device__ float g_cw[EMAX];
__device__ float g_bufA[(size_t)NMAX * 128];
__device__ float g_bufB[(size_t)NMAX * 128];
__device__ float g_zg[(size_t)NMAX * 2];
__device__ float g_Wcat[128 * 128];
__device__ float g_bcat[128];

// ---------------------------------------------------------------
__global__ void k_zero(int* p, int n) {
    int i = blockIdx.x * blockDim.x + threadIdx.x;
    if (i < n) p[i] = 0;
}

__global__ void k_count(const int* __restrict__ dst, int* __restrict__ cnt, int E) {
    int e = blockIdx.x * blockDim.x + threadIdx.x;
    if (e < E) atomicAdd(&cnt[dst[e]], 1);
}

// single-block exclusive scan over n (<=NMAX) + dinv computation
__global__ void k_scan(const int* __restrict__ cnt, int* __restrict__ off,
                       int* __restrict__ cur, float* __restrict__ dinv, int n) {
    __shared__ int sh[1024];
    __shared__ int carry;
    if (threadIdx.x == 0) carry = 0;
    __syncthreads();
    for (int base = 0; base < n; base += 1024) {
        int i = base + threadIdx.x;
        int v = (i < n) ? cnt[i] : 0;
        sh[threadIdx.x] = v;
        __syncthreads();
        for (int d = 1; d < 1024; d <<= 1) {
            int t = 0;
            if (threadIdx.x >= (unsigned)d) t = sh[threadIdx.x - d];
            __syncthreads();
            sh[threadIdx.x] += t;
            __syncthreads();
        }
        int incl = sh[threadIdx.x];
        int c = carry;
        if (i < n) {
            int o = c + incl - v;
            off[i] = o;
            cur[i] = o;
            dinv[i] = rsqrtf((float)(v + 1));   // self-loop => deg >= 1
        }
        __syncthreads();
        if (threadIdx.x == 0) carry = c + sh[1023];
        __syncthreads();
    }
    if (threadIdx.x == 0) off[n] = carry;
}

__global__ void k_fill(const int* __restrict__ src, const int* __restrict__ dst,
                       const float* __restrict__ dinv, int* __restrict__ cur,
                       int* __restrict__ csrc, float* __restrict__ cw, int E) {
    int e = blockIdx.x * blockDim.x + threadIdx.x;
    if (e >= E) return;
    int s = src[e], d = dst[e];
    int p = atomicAdd(&cur[d], 1);
    csrc[p] = s;
    cw[p] = dinv[s] * dinv[d];
}

__global__ void k_wcat(const float* __restrict__ Wmu, const float* __restrict__ Wls,
                       const float* __restrict__ bmu, const float* __restrict__ bls,
                       float* __restrict__ Wcat, float* __restrict__ bcat) {
    int i = blockIdx.x * blockDim.x + threadIdx.x;
    if (i < 128 * 128) {
        int k = i >> 7, p = i & 127;
        Wcat[i] = (p < 64) ? Wmu[k * 64 + p] : Wls[k * 64 + (p - 64)];
    }
    if (i < 128) bcat[i] = (i < 64) ? bmu[i] : bls[i - 64];
}

// C[n x 128] = A[n x K] * W[K x 128], fp32 SIMT, BM=64, BK=16, 256 threads
template <int K>
__global__ void k_gemm(const float* __restrict__ A, const float* __restrict__ W,
                       float* __restrict__ C, int n) {
    __shared__ float As[16][64];
    __shared__ float Ws[16][128];
    int tid = threadIdx.x;
    int blockRow = blockIdx.x * 64;
    int ty = tid >> 5;            // 0..7  (uniform per warp)
    int col4 = (tid & 31) * 4;    // 0..124
    float acc[8][4];
#pragma unroll
    for (int r = 0; r < 8; r++)
#pragma unroll
        for (int c = 0; c < 4; c++) acc[r][c] = 0.f;

    for (int k0 = 0; k0 < K; k0 += 16) {
        // load A tile: 64 rows x 16 k
        int rl = tid >> 2;
        int kk4 = (tid & 3) * 4;
        int row = blockRow + rl;
        float4 av = make_float4(0.f, 0.f, 0.f, 0.f);
        if (row < n) av = *(const float4*)(A + (size_t)row * K + k0 + kk4);
        As[kk4 + 0][rl] = av.x;
        As[kk4 + 1][rl] = av.y;
        As[kk4 + 2][rl] = av.z;
        As[kk4 + 3][rl] = av.w;
        // load W tile: 16 rows x 128
        int kw = tid >> 4;
        int c8 = (tid & 15) * 8;
        float4 w0 = *(const float4*)(W + (size_t)(k0 + kw) * 128 + c8);
        float4 w1 = *(const float4*)(W + (size_t)(k0 + kw) * 128 + c8 + 4);
        *(float4*)&Ws[kw][c8] = w0;
        *(float4*)&Ws[kw][c8 + 4] = w1;
        __syncthreads();
#pragma unroll
        for (int kk = 0; kk < 16; kk++) {
            float4 wv = *(const float4*)&Ws[kk][col4];
#pragma unroll
            for (int r = 0; r < 8; r++) {
                float a = As[kk][ty * 8 + r];
                acc[r][0] += a * wv.x;
                acc[r][1] += a * wv.y;
                acc[r][2] += a * wv.z;
                acc[r][3] += a * wv.w;
            }
        }
        __syncthreads();
    }
#pragma unroll
    for (int r = 0; r < 8; r++) {
        int row = blockRow + ty * 8 + r;
        if (row < n)
            *(float4*)(C + (size_t)row * 128 + col4) =
                make_float4(acc[r][0], acc[r][1], acc[r][2], acc[r][3]);
    }
}

// warp-per-node CSR aggregation, 128-wide features.
// out = sum_{e in in(v)} w_e * feat[src_e] + dinv[v]^2 * feat[v] + bias
// split: cols 0..63 -> outA[v*64+c], 64..127 -> outB[v*64+c-64]
__global__ void k_agg128(const float* __restrict__ feat, const int* __restrict__ off,
                         const int* __restrict__ csrc, const float* __restrict__ cw,
                         const float* __restrict__ dinv, const float* __restrict__ bias,
                         float* __restrict__ outA, float* __restrict__ outB,
                         int n, int do_relu, int split) {
    int gw = (blockIdx.x * blockDim.x + threadIdx.x) >> 5;
    int lane = threadIdx.x & 31;
    int nw = (gridDim.x * blockDim.x) >> 5;
    float4 bv = *(const float4*)(bias + lane * 4);
    for (int v = gw; v < n; v += nw) {
        float dv = dinv[v];
        float sw = dv * dv;
        float4 a = __ldg((const float4*)(feat + (size_t)v * 128) + lane);
        float ax = sw * a.x, ay = sw * a.y, az = sw * a.z, aw = sw * a.w;
        int e = off[v], t = off[v + 1];
        for (; e + 1 < t; e += 2) {
            int u0 = __ldg(csrc + e);
            int u1 = __ldg(csrc + e + 1);
            float w0 = __ldg(cw + e);
            float w1 = __ldg(cw + e + 1);
            float4 g0 = __ldg((const float4*)(feat + (size_t)u0 * 128) + lane);
            float4 g1 = __ldg((const float4*)(feat + (size_t)u1 * 128) + lane);
            ax += w0 * g0.x + w1 * g1.x;
            ay += w0 * g0.y + w1 * g1.y;
            az += w0 * g0.z + w1 * g1.z;
            aw += w0 * g0.w + w1 * g1.w;
        }
        if (e < t) {
            int u0 = __ldg(csrc + e);
            float w0 = __ldg(cw + e);
            float4 g0 = __ldg((const float4*)(feat + (size_t)u0 * 128) + lane);
            ax += w0 * g0.x;
            ay += w0 * g0.y;
            az += w0 * g0.z;
            aw += w0 * g0.w;
        }
        ax += bv.x; ay += bv.y; az += bv.z; aw += bv.w;
        if (do_relu) {
            ax = fmaxf(ax, 0.f); ay = fmaxf(ay, 0.f);
            az = fmaxf(az, 0.f); aw = fmaxf(aw, 0.f);
        }
        float4 res = make_float4(ax, ay, az, aw);
        if (!split) {
            *(float4*)(outA + (size_t)v * 128 + lane * 4) = res;
        } else if (lane < 16) {
            *(float4*)(outA + (size_t)v * 64 + lane * 4) = res;
        } else {
            *(float4*)(outB + (size_t)v * 64 + lane * 4 - 64) = res;
        }
    }
}

__global__ void k_z(const float* __restrict__ eps, const float* __restrict__ mu,
                    const float* __restrict__ lv, float* __restrict__ z, int total) {
    int i = blockIdx.x * blockDim.x + threadIdx.x;
    if (i < total) z[i] = eps[i] * expf(0.5f * lv[i]) + mu[i];
}

// per-node small decoders: zg = z@W_g (no bias, aggregated later), label = z@W_lc + b_lc
__global__ void k_dec_small(const float* __restrict__ z, const float* __restrict__ Wg,
                            const float* __restrict__ Wlc, const float* __restrict__ blc,
                            float* __restrict__ zg, float* __restrict__ out_label, int n) {
    int gw = (blockIdx.x * blockDim.x + threadIdx.x) >> 5;
    int lane = threadIdx.x & 31;
    int nw = (gridDim.x * blockDim.x) >> 5;
    float wg00 = __ldg(Wg + lane * 2);
    float wg01 = __ldg(Wg + lane * 2 + 1);
    float wg10 = __ldg(Wg + (lane + 32) * 2);
    float wg11 = __ldg(Wg + (lane + 32) * 2 + 1);
    float wl0 = __ldg(Wlc + lane);
    float wl1 = __ldg(Wlc + lane + 32);
    float bl = __ldg(blc);
    for (int v = gw; v < n; v += nw) {
        float z0 = z[(size_t)v * 64 + lane];
        float z1 = z[(size_t)v * 64 + 32 + lane];
        float g0 = z0 * wg00 + z1 * wg10;
        float g1 = z0 * wg01 + z1 * wg11;
        float l = z0 * wl0 + z1 * wl1;
#pragma unroll
        for (int o = 16; o; o >>= 1) {
            g0 += __shfl_xor_sync(0xFFFFFFFFu, g0, o);
            g1 += __shfl_xor_sync(0xFFFFFFFFu, g1, o);
            l += __shfl_xor_sync(0xFFFFFFFFu, l, o);
        }
        if (lane == 0) {
            zg[(size_t)v * 2] = g0;
            zg[(size_t)v * 2 + 1] = g1;
            out_label[v] = l + bl;
        }
    }
}

// aggregate 2-wide gender logits + gumbel-softmax (hard, straight-through)
__global__ void k_agg2_gumbel(const float* __restrict__ zg, const int* __restrict__ off,
                              const int* __restrict__ csrc, const float* __restrict__ cw,
                              const float* __restrict__ dinv, const float* __restrict__ bg,
                              const float* __restrict__ uu, float* __restrict__ out_g, int n) {
    int gw = (blockIdx.x * blockDim.x + threadIdx.x) >> 5;
    int lane = threadIdx.x & 31;
    int nw = (gridDim.x * blockDim.x) >> 5;
    for (int v = gw; v < n; v += nw) {
        float a0 = 0.f, a1 = 0.f;
        int s = off[v], t = off[v + 1];
        for (int e = s + lane; e < t; e += 32) {
            int u = __ldg(csrc + e);
            float w = __ldg(cw + e);
            a0 += w * zg[(size_t)u * 2];
            a1 += w * zg[(size_t)u * 2 + 1];
        }
        if (lane == 0) {
            float dv = dinv[v];
            float swv = dv * dv;
            a0 += swv * zg[(size_t)v * 2];
            a1 += swv * zg[(size_t)v * 2 + 1];
        }
#pragma unroll
        for (int o = 16; o; o >>= 1) {
            a0 += __shfl_xor_sync(0xFFFFFFFFu, a0, o);
            a1 += __shfl_xor_sync(0xFFFFFFFFu, a1, o);
        }
        if (lane == 0) {
            float l0 = a0 + bg[0], l1 = a1 + bg[1];
            float u0 = uu[(size_t)v * 2], u1 = uu[(size_t)v * 2 + 1];
            float gn0 = -logf(-logf(u0 + 1e-20f) + 1e-20f);
            float gn1 = -logf(-logf(u1 + 1e-20f) + 1e-20f);
            float s0 = l0 + gn0, s1 = l1 + gn1;
            float m = fmaxf(s0, s1);
            float e0 = expf(s0 - m), e1 = expf(s1 - m);
            float inv = 1.f / (e0 + e1);
            float y0 = e0 * inv, y1 = e1 * inv;
            float h0 = (s1 > s0) ? 0.f : 1.f;   // argmax; tie -> index 0 (matches jnp.argmax)
            float h1 = 1.f - h0;
            out_g[(size_t)v * 2] = (h0 - y0) + y0;
            out_g[(size_t)v * 2 + 1] = (h1 - y1) + y1;
        }
    }
}

// ---------------------------------------------------------------
extern "C" void kernel_launch(void* const* d_in, const int* in_sizes, int n_in,
                              void* d_out, int out_size) {
    const float* x   = (const float*)d_in[0];
    const int*   ei  = (const int*)d_in[1];
    const float* eps = (const float*)d_in[2];
    const float* u   = (const float*)d_in[3];
    const float* W1  = (const float*)d_in[4];
    const float* b1  = (const float*)d_in[5];
    const float* Wmu = (const float*)d_in[6];
    const float* bmu = (const float*)d_in[7];
    const float* Wls = (const float*)d_in[8];
    const float* bls = (const float*)d_in[9];
    const float* Wdx = (const float*)d_in[10];
    const float* bdx = (const float*)d_in[11];
    const float* Wg  = (const float*)d_in[12];
    const float* bg  = (const float*)d_in[13];
    const float* Wlc = (const float*)d_in[14];
    const float* blc = (const float*)d_in[15];

    int n = in_sizes[0] / 128;     // 50000
    int E = in_sizes[1] / 2;       // 1.6M
    const int* esrc = ei;
    const int* edst = ei + E;

    float* out = (float*)d_out;
    size_t nn = (size_t)n;
    float* o_recon  = out;
    float* o_gender = out + nn * 128;
    float* o_label  = out + nn * 130;
    float* o_mu     = out + nn * 131;
    float* o_lv     = out + nn * 195;
    float* o_z      = out + nn * 259;

    int *cnt, *off, *cur, *csrc;
    float *dinv, *cw, *bufA, *bufB, *zg, *Wcat, *bcat;
    cudaGetSymbolAddress((void**)&cnt, g_cnt);
    cudaGetSymbolAddress((void**)&off, g_off);
    cudaGetSymbolAddress((void**)&cur, g_cur);
    cudaGetSymbolAddress((void**)&dinv, g_dinv);
    cudaGetSymbolAddress((void**)&csrc, g_csrc);
    cudaGetSymbolAddress((void**)&cw, g_cw);
    cudaGetSymbolAddress((void**)&bufA, g_bufA);
    cudaGetSymbolAddress((void**)&bufB, g_bufB);
    cudaGetSymbolAddress((void**)&zg, g_zg);
    cudaGetSymbolAddress((void**)&Wcat, g_Wcat);
    cudaGetSymbolAddress((void**)&bcat, g_bcat);

    int eb = (E + 255) / 256;
    int gb = (n + 63) / 64;

    // CSR build (dst-grouped) + dinv
    k_zero<<<(n + 255) / 256, 256>>>(cnt, n);
    k_count<<<eb, 256>>>(edst, cnt, E);
    k_scan<<<1, 1024>>>(cnt, off, cur, dinv, n);
    k_fill<<<eb, 256>>>(esrc, edst, dinv, cur, csrc, cw, E);
    k_wcat<<<(128 * 128 + 255) / 256, 256>>>(Wmu, Wls, bmu, bls, Wcat, bcat);

    // encoder layer 1: h = relu(agg(x@W1) + b1)
    k_gemm<128><<<gb, 256>>>(x, W1, bufA, n);
    k_agg128<<<1024, 256>>>(bufA, off, csrc, cw, dinv, b1, bufB, nullptr, n, 1, 0);

    // mu / logvar (fused 128-wide): hml = h@[Wmu|Wls]; split-agg into mu/logvar
    k_gemm<128><<<gb, 256>>>(bufB, Wcat, bufA, n);
    k_agg128<<<1024, 256>>>(bufA, off, csrc, cw, dinv, bcat, o_mu, o_lv, n, 0, 1);

    // reparameterize
    k_z<<<(n * 64 + 255) / 256, 256>>>(eps, o_mu, o_lv, o_z, n * 64);

    // recon_x = agg(z@W_dx) + b_dx
    k_gemm<64><<<gb, 256>>>(o_z, Wdx, bufA, n);
    k_agg128<<<1024, 256>>>(bufA, off, csrc, cw, dinv, bdx, o_recon, nullptr, n, 0, 0);

    // small decoders + gumbel
    k_dec_small<<<256, 256>>>(o_z, Wg, Wlc, blc, zg, o_label, n);
    k_agg2_gumbel<<<512, 256>>>(zg, off, csrc, cw, dinv, bg, u, o_gender, n);
}

// round 7
// speedup vs baseline: 1.1147x; 1.1147x over previous
#include <cuda_runtime.h>
#include <math.h>

#define NMAX 50000
#define EMAX 1600000

// ---- static device scratch (no runtime allocation allowed) ----
__device__ int   g_cnt[NMAX];
__device__ int   g_off[NMAX + 1];
__device__ int   g_cur[NMAX];
__device__ float g_dinv[NMAX];
__device__ int   g_csrc[EMAX];
__device__ float g_cw[EMAX];
__device__ float g_bufA[(size_t)NMAX * 128];
__device__ float g_bufB[(size_t)NMAX * 128];
__device__ float g_Wcat[128 * 128];
__device__ float g_bcat[128];

// ---------------------------------------------------------------
__global__ void k_zero(int* p, int n) {
    int i = blockIdx.x * blockDim.x + threadIdx.x;
    if (i < n) p[i] = 0;
}

__global__ void k_count(const int* __restrict__ dst, int* __restrict__ cnt, int E) {
    int e = blockIdx.x * blockDim.x + threadIdx.x;
    if (e < E) atomicAdd(&cnt[dst[e]], 1);
}

// single-block warp-shuffle exclusive scan over n (<=NMAX) + dinv computation
__global__ void k_scan(const int* __restrict__ cnt, int* __restrict__ off,
                       int* __restrict__ cur, float* __restrict__ dinv, int n) {
    __shared__ int wsum[32];
    __shared__ int s_carry;
    int lane = threadIdx.x & 31;
    int warp = threadIdx.x >> 5;
    if (threadIdx.x == 0) s_carry = 0;
    __syncthreads();
    for (int base = 0; base < n; base += 1024) {
        int i = base + threadIdx.x;
        int v = (i < n) ? cnt[i] : 0;
        int x = v;
#pragma unroll
        for (int o = 1; o < 32; o <<= 1) {
            int t = __shfl_up_sync(0xFFFFFFFFu, x, o);
            if (lane >= o) x += t;
        }
        if (lane == 31) wsum[warp] = x;
        __syncthreads();
        if (warp == 0) {
            int y = wsum[lane];
#pragma unroll
            for (int o = 1; o < 32; o <<= 1) {
                int t = __shfl_up_sync(0xFFFFFFFFu, y, o);
                if (lane >= o) y += t;
            }
            wsum[lane] = y;
        }
        __syncthreads();
        int wpre = (warp == 0) ? 0 : wsum[warp - 1];
        int carry = s_carry;
        int incl = carry + wpre + x;
        if (i < n) {
            int o = incl - v;
            off[i] = o;
            cur[i] = o;
            dinv[i] = rsqrtf((float)(v + 1));   // self-loop => deg >= 1
        }
        __syncthreads();
        if (threadIdx.x == 1023) s_carry = incl;
        __syncthreads();
    }
    if (threadIdx.x == 0) off[n] = s_carry;
}

__global__ void k_fill(const int* __restrict__ src, const int* __restrict__ dst,
                       const float* __restrict__ dinv, int* __restrict__ cur,
                       int* __restrict__ csrc, float* __restrict__ cw, int E) {
    int e = blockIdx.x * blockDim.x + threadIdx.x;
    if (e >= E) return;
    int s = src[e], d = dst[e];
    int p = atomicAdd(&cur[d], 1);
    csrc[p] = s;
    cw[p] = dinv[s] * dinv[d];
}

__global__ void k_wcat(const float* __restrict__ Wmu, const float* __restrict__ Wls,
                       const float* __restrict__ bmu, const float* __restrict__ bls,
                       float* __restrict__ Wcat, float* __restrict__ bcat) {
    int i = blockIdx.x * blockDim.x + threadIdx.x;
    if (i < 128 * 128) {
        int k = i >> 7, p = i & 127;
        Wcat[i] = (p < 64) ? Wmu[k * 64 + p] : Wls[k * 64 + (p - 64)];
    }
    if (i < 128) bcat[i] = (i < 64) ? bmu[i] : bls[i - 64];
}

// C[n x 128] = A[n x K] * W[K x 128] + bias, fp32 SIMT, BM=64, BK=16, 256 threads
// EPI 0: C = acc + bias
// EPI 1: C = relu(acc + bias)
// EPI 2: split: col<64 -> C[row*64+col], col>=64 -> C2[row*64+col-64]  (both + bias)
template <int K, int EPI>
__global__ void k_gemm(const float* __restrict__ A, const float* __restrict__ W,
                       const float* __restrict__ bias,
                       float* __restrict__ C, float* __restrict__ C2, int n) {
    __shared__ float As[16][64];
    __shared__ float Ws[16][128];
    int tid = threadIdx.x;
    int blockRow = blockIdx.x * 64;
    int ty = tid >> 5;            // 0..7  (uniform per warp)
    int col4 = (tid & 31) * 4;    // 0..124
    float acc[8][4];
#pragma unroll
    for (int r = 0; r < 8; r++)
#pragma unroll
        for (int c = 0; c < 4; c++) acc[r][c] = 0.f;

    for (int k0 = 0; k0 < K; k0 += 16) {
        int rl = tid >> 2;
        int kk4 = (tid & 3) * 4;
        int row = blockRow + rl;
        float4 av = make_float4(0.f, 0.f, 0.f, 0.f);
        if (row < n) av = *(const float4*)(A + (size_t)row * K + k0 + kk4);
        As[kk4 + 0][rl] = av.x;
        As[kk4 + 1][rl] = av.y;
        As[kk4 + 2][rl] = av.z;
        As[kk4 + 3][rl] = av.w;
        int kw = tid >> 4;
        int c8 = (tid & 15) * 8;
        float4 w0 = *(const float4*)(W + (size_t)(k0 + kw) * 128 + c8);
        float4 w1 = *(const float4*)(W + (size_t)(k0 + kw) * 128 + c8 + 4);
        *(float4*)&Ws[kw][c8] = w0;
        *(float4*)&Ws[kw][c8 + 4] = w1;
        __syncthreads();
#pragma unroll
        for (int kk = 0; kk < 16; kk++) {
            float4 wv = *(const float4*)&Ws[kk][col4];
#pragma unroll
            for (int r = 0; r < 8; r++) {
                float a = As[kk][ty * 8 + r];
                acc[r][0] += a * wv.x;
                acc[r][1] += a * wv.y;
                acc[r][2] += a * wv.z;
                acc[r][3] += a * wv.w;
            }
        }
        __syncthreads();
    }
    float4 bv = *(const float4*)(bias + col4);
#pragma unroll
    for (int r = 0; r < 8; r++) {
        int row = blockRow + ty * 8 + r;
        if (row >= n) continue;
        float4 res = make_float4(acc[r][0] + bv.x, acc[r][1] + bv.y,
                                 acc[r][2] + bv.z, acc[r][3] + bv.w);
        if (EPI == 1) {
            res.x = fmaxf(res.x, 0.f); res.y = fmaxf(res.y, 0.f);
            res.z = fmaxf(res.z, 0.f); res.w = fmaxf(res.w, 0.f);
        }
        if (EPI == 2) {
            if (col4 < 64)
                *(float4*)(C + (size_t)row * 64 + col4) = res;
            else
                *(float4*)(C2 + (size_t)row * 64 + col4 - 64) = res;
        } else {
            *(float4*)(C + (size_t)row * 128 + col4) = res;
        }
    }
}

// warp-per-node CSR aggregation, 128-wide features (no bias):
// out[v] = sum_{e in in(v)} w_e * feat[src_e] + dinv[v]^2 * feat[v]
__global__ void k_agg128(const float* __restrict__ feat, const int* __restrict__ off,
                         const int* __restrict__ csrc, const float* __restrict__ cw,
                         const float* __restrict__ dinv, float* __restrict__ out, int n) {
    int gw = (blockIdx.x * blockDim.x + threadIdx.x) >> 5;
    int lane = threadIdx.x & 31;
    int nw = (gridDim.x * blockDim.x) >> 5;
    for (int v = gw; v < n; v += nw) {
        float dv = dinv[v];
        float sw = dv * dv;
        float4 a = __ldg((const float4*)(feat + (size_t)v * 128) + lane);
        float ax = sw * a.x, ay = sw * a.y, az = sw * a.z, aw = sw * a.w;
        int e = off[v], t = off[v + 1];
        for (; e + 3 < t; e += 4) {
            int u0 = __ldg(csrc + e);
            int u1 = __ldg(csrc + e + 1);
            int u2 = __ldg(csrc + e + 2);
            int u3 = __ldg(csrc + e + 3);
            float w0 = __ldg(cw + e);
            float w1 = __ldg(cw + e + 1);
            float w2 = __ldg(cw + e + 2);
            float w3 = __ldg(cw + e + 3);
            float4 g0 = __ldg((const float4*)(feat + (size_t)u0 * 128) + lane);
            float4 g1 = __ldg((const float4*)(feat + (size_t)u1 * 128) + lane);
            float4 g2 = __ldg((const float4*)(feat + (size_t)u2 * 128) + lane);
            float4 g3 = __ldg((const float4*)(feat + (size_t)u3 * 128) + lane);
            ax += w0 * g0.x + w1 * g1.x + w2 * g2.x + w3 * g3.x;
            ay += w0 * g0.y + w1 * g1.y + w2 * g2.y + w3 * g3.y;
            az += w0 * g0.z + w1 * g1.z + w2 * g2.z + w3 * g3.z;
            aw += w0 * g0.w + w1 * g1.w + w2 * g2.w + w3 * g3.w;
        }
        for (; e < t; e++) {
            int u0 = __ldg(csrc + e);
            float w0 = __ldg(cw + e);
            float4 g0 = __ldg((const float4*)(feat + (size_t)u0 * 128) + lane);
            ax += w0 * g0.x;
            ay += w0 * g0.y;
            az += w0 * g0.z;
            aw += w0 * g0.w;
        }
        *(float4*)(out + (size_t)v * 128 + lane * 4) = make_float4(ax, ay, az, aw);
    }
}

// fused reparameterize + label classifier (warp-per-node; lane owns cols 2l, 2l+1)
// z = eps * exp(0.5*logvar) + mu ; label = z @ W_lc + b_lc
__global__ void k_z_label(const float* __restrict__ eps, const float* __restrict__ mu,
                          const float* __restrict__ lv, const float* __restrict__ Wlc,
                          const float* __restrict__ blc, float* __restrict__ z,
                          float* __restrict__ out_label, int n) {
    int gw = (blockIdx.x * blockDim.x + threadIdx.x) >> 5;
    int lane = threadIdx.x & 31;
    int nw = (gridDim.x * blockDim.x) >> 5;
    float wl0 = __ldg(Wlc + 2 * lane);
    float wl1 = __ldg(Wlc + 2 * lane + 1);
    float bl = __ldg(blc);
    for (int v = gw; v < n; v += nw) {
        float2 m = *(const float2*)(mu + (size_t)v * 64 + 2 * lane);
        float2 lg = *(const float2*)(lv + (size_t)v * 64 + 2 * lane);
        float2 ee = *(const float2*)(eps + (size_t)v * 64 + 2 * lane);
        float z0 = ee.x * expf(0.5f * lg.x) + m.x;
        float z1 = ee.y * expf(0.5f * lg.y) + m.y;
        *(float2*)(z + (size_t)v * 64 + 2 * lane) = make_float2(z0, z1);
        float l = z0 * wl0 + z1 * wl1;
#pragma unroll
        for (int o = 16; o; o >>= 1) l += __shfl_xor_sync(0xFFFFFFFFu, l, o);
        if (lane == 0) out_label[v] = l + bl;
    }
}

// 64-wide aggregation of z (shared by recon GEMM and gender head) with fused
// gender logits + Gumbel-softmax epilogue. Lane owns cols 2l, 2l+1 (float2).
__global__ void k_agg64_gumbel(const float* __restrict__ z, const int* __restrict__ off,
                               const int* __restrict__ csrc, const float* __restrict__ cw,
                               const float* __restrict__ dinv, const float* __restrict__ Wg,
                               const float* __restrict__ bg, const float* __restrict__ uu,
                               float* __restrict__ aggz, float* __restrict__ out_g, int n) {
    int gw = (blockIdx.x * blockDim.x + threadIdx.x) >> 5;
    int lane = threadIdx.x & 31;
    int nw = (gridDim.x * blockDim.x) >> 5;
    float wg0a = __ldg(Wg + (2 * lane) * 2);
    float wg0b = __ldg(Wg + (2 * lane) * 2 + 1);
    float wg1a = __ldg(Wg + (2 * lane + 1) * 2);
    float wg1b = __ldg(Wg + (2 * lane + 1) * 2 + 1);
    for (int v = gw; v < n; v += nw) {
        float dv = dinv[v];
        float sw = dv * dv;
        float2 a = __ldg((const float2*)(z + (size_t)v * 64) + lane);
        float ax = sw * a.x, ay = sw * a.y;
        int e = off[v], t = off[v + 1];
        for (; e + 3 < t; e += 4) {
            int u0 = __ldg(csrc + e);
            int u1 = __ldg(csrc + e + 1);
            int u2 = __ldg(csrc + e + 2);
            int u3 = __ldg(csrc + e + 3);
            float w0 = __ldg(cw + e);
            float w1 = __ldg(cw + e + 1);
            float w2 = __ldg(cw + e + 2);
            float w3 = __ldg(cw + e + 3);
            float2 g0 = __ldg((const float2*)(z + (size_t)u0 * 64) + lane);
            float2 g1 = __ldg((const float2*)(z + (size_t)u1 * 64) + lane);
            float2 g2 = __ldg((const float2*)(z + (size_t)u2 * 64) + lane);
            float2 g3 = __ldg((const float2*)(z + (size_t)u3 * 64) + lane);
            ax += w0 * g0.x + w1 * g1.x + w2 * g2.x + w3 * g3.x;
            ay += w0 * g0.y + w1 * g1.y + w2 * g2.y + w3 * g3.y;
        }
        for (; e < t; e++) {
            int u0 = __ldg(csrc + e);
            float w0 = __ldg(cw + e);
            float2 g0 = __ldg((const float2*)(z + (size_t)u0 * 64) + lane);
            ax += w0 * g0.x;
            ay += w0 * g0.y;
        }
        *(float2*)(aggz + (size_t)v * 64 + 2 * lane) = make_float2(ax, ay);
        // gender logits: aggz @ W_g
        float g0 = ax * wg0a + ay * wg1a;
        float g1 = ax * wg0b + ay * wg1b;
#pragma unroll
        for (int o = 16; o; o >>= 1) {
            g0 += __shfl_xor_sync(0xFFFFFFFFu, g0, o);
            g1 += __shfl_xor_sync(0xFFFFFFFFu, g1, o);
        }
        if (lane == 0) {
            float l0 = g0 + bg[0], l1 = g1 + bg[1];
            float u0 = uu[(size_t)v * 2], u1 = uu[(size_t)v * 2 + 1];
            float gn0 = -logf(-logf(u0 + 1e-20f) + 1e-20f);
            float gn1 = -logf(-logf(u1 + 1e-20f) + 1e-20f);
            float s0 = l0 + gn0, s1 = l1 + gn1;
            float m = fmaxf(s0, s1);
            float e0 = expf(s0 - m), e1 = expf(s1 - m);
            float inv = 1.f / (e0 + e1);
            float y0 = e0 * inv, y1 = e1 * inv;
            float h0 = (s1 > s0) ? 0.f : 1.f;   // argmax; tie -> index 0
            float h1 = 1.f - h0;
            out_g[(size_t)v * 2] = (h0 - y0) + y0;
            out_g[(size_t)v * 2 + 1] = (h1 - y1) + y1;
        }
    }
}

// ---------------------------------------------------------------
extern "C" void kernel_launch(void* const* d_in, const int* in_sizes, int n_in,
                              void* d_out, int out_size) {
    const float* x   = (const float*)d_in[0];
    const int*   ei  = (const int*)d_in[1];
    const float* eps = (const float*)d_in[2];
    const float* u   = (const float*)d_in[3];
    const float* W1  = (const float*)d_in[4];
    const float* b1  = (const float*)d_in[5];
    const float* Wmu = (const float*)d_in[6];
    const float* bmu = (const float*)d_in[7];
    const float* Wls = (const float*)d_in[8];
    const float* bls = (const float*)d_in[9];
    const float* Wdx = (const float*)d_in[10];
    const float* bdx = (const float*)d_in[11];
    const float* Wg  = (const float*)d_in[12];
    const float* bg  = (const float*)d_in[13];
    const float* Wlc = (const float*)d_in[14];
    const float* blc = (const float*)d_in[15];

    int n = in_sizes[0] / 128;     // 50000
    int E = in_sizes[1] / 2;       // 1.6M
    const int* esrc = ei;
    const int* edst = ei + E;

    float* out = (float*)d_out;
    size_t nn = (size_t)n;
    float* o_recon  = out;
    float* o_gender = out + nn * 128;
    float* o_label  = out + nn * 130;
    float* o_mu     = out + nn * 131;
    float* o_lv     = out + nn * 195;
    float* o_z      = out + nn * 259;

    int *cnt, *off, *cur, *csrc;
    float *dinv, *cw, *bufA, *bufB, *Wcat, *bcat;
    cudaGetSymbolAddress((void**)&cnt, g_cnt);
    cudaGetSymbolAddress((void**)&off, g_off);
    cudaGetSymbolAddress((void**)&cur, g_cur);
    cudaGetSymbolAddress((void**)&dinv, g_dinv);
    cudaGetSymbolAddress((void**)&csrc, g_csrc);
    cudaGetSymbolAddress((void**)&cw, g_cw);
    cudaGetSymbolAddress((void**)&bufA, g_bufA);
    cudaGetSymbolAddress((void**)&bufB, g_bufB);
    cudaGetSymbolAddress((void**)&Wcat, g_Wcat);
    cudaGetSymbolAddress((void**)&bcat, g_bcat);

    int eb = (E + 255) / 256;
    int gb = (n + 63) / 64;

    // CSR build (dst-grouped) + dinv
    k_zero<<<(n + 255) / 256, 256>>>(cnt, n);
    k_count<<<eb, 256>>>(edst, cnt, E);
    k_scan<<<1, 1024>>>(cnt, off, cur, dinv, n);
    k_fill<<<eb, 256>>>(esrc, edst, dinv, cur, csrc, cw, E);
    k_wcat<<<(128 * 128 + 255) / 256, 256>>>(Wmu, Wls, bmu, bls, Wcat, bcat);

    // aggregation commutes with the dense projection: agg(x@W) == agg(x)@W.
    // encoder layer 1: h = relu(agg(x)@W1 + b1)
    k_agg128<<<1024, 256>>>(x, off, csrc, cw, dinv, bufA, n);
    k_gemm<128, 1><<<gb, 256>>>(bufA, W1, b1, bufB, nullptr, n);

    // mu / logvar: aggH = agg(h); [mu|lv] = aggH@Wcat + bcat (split epilogue)
    k_agg128<<<1024, 256>>>(bufB, off, csrc, cw, dinv, bufA, n);
    k_gemm<128, 2><<<gb, 256>>>(bufA, Wcat, bcat, o_mu, o_lv, n);

    // reparameterize + label head (z @ W_lc + b_lc), fused
    k_z_label<<<1024, 256>>>(eps, o_mu, o_lv, Wlc, blc, o_z, o_label, n);

    // aggZ = agg(z) [64-wide], shared by recon and gender; gender+gumbel fused
    k_agg64_gumbel<<<1024, 256>>>(o_z, off, csrc, cw, dinv, Wg, bg, u, bufA, o_gender, n);

    // recon_x = aggZ @ W_dx + b_dx
    k_gemm<64, 0><<<gb, 256>>>(bufA, Wdx, bdx, o_recon, nullptr, n);
}

// round 13
// speedup vs baseline: 1.2564x; 1.1271x over previous
#include <cuda_runtime.h>
#include <cuda_fp16.h>
#include <math.h>

#define NMAX 50000
#define EMAX 1600000

// ---- static device scratch (no runtime allocation allowed) ----
__device__ int    g_cnt[NMAX];
__device__ int    g_off[NMAX + 1];
__device__ int    g_cur[NMAX];
__device__ float  g_dinv[NMAX];
__device__ int2   g_epack[EMAX];                    // {src, weight-bits}
__device__ float  g_bufA[(size_t)NMAX * 128];
__device__ __half g_xh[(size_t)NMAX * 128];
__device__ __half g_hh[(size_t)NMAX * 128];
__device__ float  g_Wcat[128 * 128];
__device__ float  g_bcat[128];

// ---------------------------------------------------------------
__global__ void k_zero(int* p, int n) {
    int i = blockIdx.x * blockDim.x + threadIdx.x;
    if (i < n) p[i] = 0;
}

__global__ void k_count(const int* __restrict__ dst, int* __restrict__ cnt, int E) {
    int e = blockIdx.x * blockDim.x + threadIdx.x;
    if (e < E) atomicAdd(&cnt[dst[e]], 1);
}

// single-block warp-shuffle exclusive scan over n (<=NMAX) + dinv computation
__global__ void k_scan(const int* __restrict__ cnt, int* __restrict__ off,
                       int* __restrict__ cur, float* __restrict__ dinv, int n) {
    __shared__ int wsum[32];
    __shared__ int s_carry;
    int lane = threadIdx.x & 31;
    int warp = threadIdx.x >> 5;
    if (threadIdx.x == 0) s_carry = 0;
    __syncthreads();
    for (int base = 0; base < n; base += 1024) {
        int i = base + threadIdx.x;
        int v = (i < n) ? cnt[i] : 0;
        int x = v;
#pragma unroll
        for (int o = 1; o < 32; o <<= 1) {
            int t = __shfl_up_sync(0xFFFFFFFFu, x, o);
            if (lane >= o) x += t;
        }
        if (lane == 31) wsum[warp] = x;
        __syncthreads();
        if (warp == 0) {
            int y = wsum[lane];
#pragma unroll
            for (int o = 1; o < 32; o <<= 1) {
                int t = __shfl_up_sync(0xFFFFFFFFu, y, o);
                if (lane >= o) y += t;
            }
            wsum[lane] = y;
        }
        __syncthreads();
        int wpre = (warp == 0) ? 0 : wsum[warp - 1];
        int carry = s_carry;
        int incl = carry + wpre + x;
        if (i < n) {
            int o = incl - v;
            off[i] = o;
            cur[i] = o;
            dinv[i] = rsqrtf((float)(v + 1));   // self-loop => deg >= 1
        }
        __syncthreads();
        if (threadIdx.x == 1023) s_carry = incl;
        __syncthreads();
    }
    if (threadIdx.x == 0) off[n] = s_carry;
}

// fill CSR with packed (src, weight) in one 8B store per edge
__global__ void k_fill(const int* __restrict__ src, const int* __restrict__ dst,
                       const float* __restrict__ dinv, int* __restrict__ cur,
                       int2* __restrict__ epack, int E) {
    int e = blockIdx.x * blockDim.x + threadIdx.x;
    if (e >= E) return;
    int s = src[e], d = dst[e];
    int p = atomicAdd(&cur[d], 1);
    epack[p] = make_int2(s, __float_as_int(dinv[s] * dinv[d]));
}

__global__ void k_wcat(const float* __restrict__ Wmu, const float* __restrict__ Wls,
                       const float* __restrict__ bmu, const float* __restrict__ bls,
                       float* __restrict__ Wcat, float* __restrict__ bcat) {
    int i = blockIdx.x * blockDim.x + threadIdx.x;
    if (i < 128 * 128) {
        int k = i >> 7, p = i & 127;
        Wcat[i] = (p < 64) ? Wmu[k * 64 + p] : Wls[k * 64 + (p - 64)];
    }
    if (i < 128) bcat[i] = (i < 64) ? bmu[i] : bls[i - 64];
}

// fp32 -> fp16 conversion (4 elems/thread)
__global__ void k_f2h(const float* __restrict__ in, __half* __restrict__ out, int total4) {
    int i = blockIdx.x * blockDim.x + threadIdx.x;
    if (i >= total4) return;
    float4 v = __ldg((const float4*)in + i);
    union { __half2 h[2]; uint2 u; } pk;
    pk.h[0] = __floats2half2_rn(v.x, v.y);
    pk.h[1] = __floats2half2_rn(v.z, v.w);
    ((uint2*)out)[i] = pk.u;
}

// load 4 halves (8B) -> float4
__device__ __forceinline__ float4 ldh4(const __half* p) {
    uint2 r = __ldg((const uint2*)p);
    __half2 h0 = *reinterpret_cast<__half2*>(&r.x);
    __half2 h1 = *reinterpret_cast<__half2*>(&r.y);
    float2 f0 = __half22float2(h0);
    float2 f1 = __half22float2(h1);
    return make_float4(f0.x, f0.y, f1.x, f1.y);
}

// C[n x 128] = A[n x K] * W[K x 128] + bias, fp32 SIMT, BM=64, BK=16, 256 threads
// EPI 0: C = acc + bias  (fp32)
// EPI 1: C = relu(acc + bias) written as __half (C reinterpreted)
// EPI 2: split: col<64 -> C[row*64+col], col>=64 -> C2[row*64+col-64]  (both + bias)
template <int K, int EPI>
__global__ void k_gemm(const float* __restrict__ A, const float* __restrict__ W,
                       const float* __restrict__ bias,
                       float* __restrict__ C, float* __restrict__ C2, int n) {
    __shared__ float As[16][64];
    __shared__ float Ws[16][128];
    int tid = threadIdx.x;
    int blockRow = blockIdx.x * 64;
    int ty = tid >> 5;            // 0..7  (uniform per warp)
    int col4 = (tid & 31) * 4;    // 0..124
    float acc[8][4];
#pragma unroll
    for (int r = 0; r < 8; r++)
#pragma unroll
        for (int c = 0; c < 4; c++) acc[r][c] = 0.f;

    for (int k0 = 0; k0 < K; k0 += 16) {
        int rl = tid >> 2;
        int kk4 = (tid & 3) * 4;
        int row = blockRow + rl;
        float4 av = make_float4(0.f, 0.f, 0.f, 0.f);
        if (row < n) av = *(const float4*)(A + (size_t)row * K + k0 + kk4);
        As[kk4 + 0][rl] = av.x;
        As[kk4 + 1][rl] = av.y;
        As[kk4 + 2][rl] = av.z;
        As[kk4 + 3][rl] = av.w;
        int kw = tid >> 4;
        int c8 = (tid & 15) * 8;
        float4 w0 = *(const float4*)(W + (size_t)(k0 + kw) * 128 + c8);
        float4 w1 = *(const float4*)(W + (size_t)(k0 + kw) * 128 + c8 + 4);
        *(float4*)&Ws[kw][c8] = w0;
        *(float4*)&Ws[kw][c8 + 4] = w1;
        __syncthreads();
#pragma unroll
        for (int kk = 0; kk < 16; kk++) {
            float4 wv = *(const float4*)&Ws[kk][col4];
#pragma unroll
            for (int r = 0; r < 8; r++) {
                float a = As[kk][ty * 8 + r];
                acc[r][0] += a * wv.x;
                acc[r][1] += a * wv.y;
                acc[r][2] += a * wv.z;
                acc[r][3] += a * wv.w;
            }
        }
        __syncthreads();
    }
    float4 bv = *(const float4*)(bias + col4);
#pragma unroll
    for (int r = 0; r < 8; r++) {
        int row = blockRow + ty * 8 + r;
        if (row >= n) continue;
        float4 res = make_float4(acc[r][0] + bv.x, acc[r][1] + bv.y,
                                 acc[r][2] + bv.z, acc[r][3] + bv.w);
        if (EPI == 1) {
            res.x = fmaxf(res.x, 0.f); res.y = fmaxf(res.y, 0.f);
            res.z = fmaxf(res.z, 0.f); res.w = fmaxf(res.w, 0.f);
            union { __half2 h[2]; uint2 u; } pk;
            pk.h[0] = __floats2half2_rn(res.x, res.y);
            pk.h[1] = __floats2half2_rn(res.z, res.w);
            __half* Ch = reinterpret_cast<__half*>(C);
            *(uint2*)(Ch + (size_t)row * 128 + col4) = pk.u;
        } else if (EPI == 2) {
            if (col4 < 64)
                *(float4*)(C + (size_t)row * 64 + col4) = res;
            else
                *(float4*)(C2 + (size_t)row * 64 + col4 - 64) = res;
        } else {
            *(float4*)(C + (size_t)row * 128 + col4) = res;
        }
    }
}

// warp-per-node CSR aggregation, 128-wide HALF features, fp32 accum/output:
// out[v] = sum_{e in in(v)} w_e * feat[src_e] + dinv[v]^2 * feat[v]
__global__ void k_agg128h(const __half* __restrict__ feat, const int* __restrict__ off,
                          const int2* __restrict__ ep, const float* __restrict__ dinv,
                          float* __restrict__ out, int n) {
    int gw = (blockIdx.x * blockDim.x + threadIdx.x) >> 5;
    int lane = threadIdx.x & 31;
    int nw = (gridDim.x * blockDim.x) >> 5;
    for (int v = gw; v < n; v += nw) {
        float dv = dinv[v];
        float sw = dv * dv;
        float4 a = ldh4(feat + (size_t)v * 128 + lane * 4);
        float ax = sw * a.x, ay = sw * a.y, az = sw * a.z, aw = sw * a.w;
        int e = off[v], t = off[v + 1];
        for (; e + 3 < t; e += 4) {
            int2 e0 = __ldg(ep + e);
            int2 e1 = __ldg(ep + e + 1);
            int2 e2 = __ldg(ep + e + 2);
            int2 e3 = __ldg(ep + e + 3);
            float4 g0 = ldh4(feat + (size_t)e0.x * 128 + lane * 4);
            float4 g1 = ldh4(feat + (size_t)e1.x * 128 + lane * 4);
            float4 g2 = ldh4(feat + (size_t)e2.x * 128 + lane * 4);
            float4 g3 = ldh4(feat + (size_t)e3.x * 128 + lane * 4);
            float w0 = __int_as_float(e0.y);
            float w1 = __int_as_float(e1.y);
            float w2 = __int_as_float(e2.y);
            float w3 = __int_as_float(e3.y);
            ax += w0 * g0.x + w1 * g1.x + w2 * g2.x + w3 * g3.x;
            ay += w0 * g0.y + w1 * g1.y + w2 * g2.y + w3 * g3.y;
            az += w0 * g0.z + w1 * g1.z + w2 * g2.z + w3 * g3.z;
            aw += w0 * g0.w + w1 * g1.w + w2 * g2.w + w3 * g3.w;
        }
        for (; e < t; e++) {
            int2 e0 = __ldg(ep + e);
            float4 g0 = ldh4(feat + (size_t)e0.x * 128 + lane * 4);
            float w0 = __int_as_float(e0.y);
            ax += w0 * g0.x;
            ay += w0 * g0.y;
            az += w0 * g0.z;
            aw += w0 * g0.w;
        }
        *(float4*)(out + (size_t)v * 128 + lane * 4) = make_float4(ax, ay, az, aw);
    }
}

// fused reparameterize + label classifier (warp-per-node; lane owns cols 2l, 2l+1)
// z = eps * exp(0.5*logvar) + mu ; label = z @ W_lc + b_lc
__global__ void k_z_label(const float* __restrict__ eps, const float* __restrict__ mu,
                          const float* __restrict__ lv, const float* __restrict__ Wlc,
                          const float* __restrict__ blc, float* __restrict__ z,
                          float* __restrict__ out_label, int n) {
    int gw = (blockIdx.x * blockDim.x + threadIdx.x) >> 5;
    int lane = threadIdx.x & 31;
    int nw = (gridDim.x * blockDim.x) >> 5;
    float wl0 = __ldg(Wlc + 2 * lane);
    float wl1 = __ldg(Wlc + 2 * lane + 1);
    float bl = __ldg(blc);
    for (int v = gw; v < n; v += nw) {
        float2 m = *(const float2*)(mu + (size_t)v * 64 + 2 * lane);
        float2 lg = *(const float2*)(lv + (size_t)v * 64 + 2 * lane);
        float2 ee = *(const float2*)(eps + (size_t)v * 64 + 2 * lane);
        float z0 = ee.x * expf(0.5f * lg.x) + m.x;
        float z1 = ee.y * expf(0.5f * lg.y) + m.y;
        *(float2*)(z + (size_t)v * 64 + 2 * lane) = make_float2(z0, z1);
        float l = z0 * wl0 + z1 * wl1;
#pragma unroll
        for (int o = 16; o; o >>= 1) l += __shfl_xor_sync(0xFFFFFFFFu, l, o);
        if (lane == 0) out_label[v] = l + bl;
    }
}

// 64-wide fp32 aggregation of z (shared by recon GEMM and gender head) with fused
// gender logits + Gumbel-softmax epilogue. Lane owns cols 2l, 2l+1 (float2).
// Kept fp32: Gumbel argmax near-ties are sensitive to logit noise.
__global__ void k_agg64_gumbel(const float* __restrict__ z, const int* __restrict__ off,
                               const int2* __restrict__ ep, const float* __restrict__ dinv,
                               const float* __restrict__ Wg, const float* __restrict__ bg,
                               const float* __restrict__ uu,
                               float* __restrict__ aggz, float* __restrict__ out_g, int n) {
    int gw = (blockIdx.x * blockDim.x + threadIdx.x) >> 5;
    int lane = threadIdx.x & 31;
    int nw = (gridDim.x * blockDim.x) >> 5;
    float wg0a = __ldg(Wg + (2 * lane) * 2);
    float wg0b = __ldg(Wg + (2 * lane) * 2 + 1);
    float wg1a = __ldg(Wg + (2 * lane + 1) * 2);
    float wg1b = __ldg(Wg + (2 * lane + 1) * 2 + 1);
    for (int v = gw; v < n; v += nw) {
        float dv = dinv[v];
        float sw = dv * dv;
        float2 a = __ldg((const float2*)(z + (size_t)v * 64) + lane);
        float ax = sw * a.x, ay = sw * a.y;
        int e = off[v], t = off[v + 1];
        for (; e + 3 < t; e += 4) {
            int2 e0 = __ldg(ep + e);
            int2 e1 = __ldg(ep + e + 1);
            int2 e2 = __ldg(ep + e + 2);
            int2 e3 = __ldg(ep + e + 3);
            float2 g0 = __ldg((const float2*)(z + (size_t)e0.x * 64) + lane);
            float2 g1 = __ldg((const float2*)(z + (size_t)e1.x * 64) + lane);
            float2 g2 = __ldg((const float2*)(z + (size_t)e2.x * 64) + lane);
            float2 g3 = __ldg((const float2*)(z + (size_t)e3.x * 64) + lane);
            float w0 = __int_as_float(e0.y);
            float w1 = __int_as_float(e1.y);
            float w2 = __int_as_float(e2.y);
            float w3 = __int_as_float(e3.y);
            ax += w0 * g0.x + w1 * g1.x + w2 * g2.x + w3 * g3.x;
            ay += w0 * g0.y + w1 * g1.y + w2 * g2.y + w3 * g3.y;
        }
        for (; e < t; e++) {
            int2 e0 = __ldg(ep + e);
            float2 g0 = __ldg((const float2*)(z + (size_t)e0.x * 64) + lane);
            float w0 = __int_as_float(e0.y);
            ax += w0 * g0.x;
            ay += w0 * g0.y;
        }
        *(float2*)(aggz + (size_t)v * 64 + 2 * lane) = make_float2(ax, ay);
        // gender logits: aggz @ W_g
        float g0 = ax * wg0a + ay * wg1a;
        float g1 = ax * wg0b + ay * wg1b;
#pragma unroll
        for (int o = 16; o; o >>= 1) {
            g0 += __shfl_xor_sync(0xFFFFFFFFu, g0, o);
            g1 += __shfl_xor_sync(0xFFFFFFFFu, g1, o);
        }
        if (lane == 0) {
            float l0 = g0 + bg[0], l1 = g1 + bg[1];
            float u0 = uu[(size_t)v * 2], u1 = uu[(size_t)v * 2 + 1];
            float gn0 = -logf(-logf(u0 + 1e-20f) + 1e-20f);
            float gn1 = -logf(-logf(u1 + 1e-20f) + 1e-20f);
            float s0 = l0 + gn0, s1 = l1 + gn1;
            float m = fmaxf(s0, s1);
            float e0 = expf(s0 - m), e1 = expf(s1 - m);
            float inv = 1.f / (e0 + e1);
            float y0 = e0 * inv, y1 = e1 * inv;
            float h0 = (s1 > s0) ? 0.f : 1.f;   // argmax; tie -> index 0
            float h1 = 1.f - h0;
            out_g[(size_t)v * 2] = (h0 - y0) + y0;
            out_g[(size_t)v * 2 + 1] = (h1 - y1) + y1;
        }
    }
}

// ---------------------------------------------------------------
extern "C" void kernel_launch(void* const* d_in, const int* in_sizes, int n_in,
                              void* d_out, int out_size) {
    const float* x   = (const float*)d_in[0];
    const int*   ei  = (const int*)d_in[1];
    const float* eps = (const float*)d_in[2];
    const float* u   = (const float*)d_in[3];
    const float* W1  = (const float*)d_in[4];
    const float* b1  = (const float*)d_in[5];
    const float* Wmu = (const float*)d_in[6];
    const float* bmu = (const float*)d_in[7];
    const float* Wls = (const float*)d_in[8];
    const float* bls = (const float*)d_in[9];
    const float* Wdx = (const float*)d_in[10];
    const float* bdx = (const float*)d_in[11];
    const float* Wg  = (const float*)d_in[12];
    const float* bg  = (const float*)d_in[13];
    const float* Wlc = (const float*)d_in[14];
    const float* blc = (const float*)d_in[15];

    int n = in_sizes[0] / 128;     // 50000
    int E = in_sizes[1] / 2;       // 1.6M
    const int* esrc = ei;
    const int* edst = ei + E;

    float* out = (float*)d_out;
    size_t nn = (size_t)n;
    float* o_recon  = out;
    float* o_gender = out + nn * 128;
    float* o_label  = out + nn * 130;
    float* o_mu     = out + nn * 131;
    float* o_lv     = out + nn * 195;
    float* o_z      = out + nn * 259;

    int *cnt, *off, *cur;
    int2* epack;
    float *dinv, *bufA, *Wcat, *bcat;
    __half *xh, *hh;
    cudaGetSymbolAddress((void**)&cnt, g_cnt);
    cudaGetSymbolAddress((void**)&off, g_off);
    cudaGetSymbolAddress((void**)&cur, g_cur);
    cudaGetSymbolAddress((void**)&dinv, g_dinv);
    cudaGetSymbolAddress((void**)&epack, g_epack);
    cudaGetSymbolAddress((void**)&bufA, g_bufA);
    cudaGetSymbolAddress((void**)&xh, g_xh);
    cudaGetSymbolAddress((void**)&hh, g_hh);
    cudaGetSymbolAddress((void**)&Wcat, g_Wcat);
    cudaGetSymbolAddress((void**)&bcat, g_bcat);

    int eb = (E + 255) / 256;
    int gb = (n + 63) / 64;

    // CSR build (dst-grouped, packed) + dinv; convert x to half for gathering
    k_zero<<<(n + 255) / 256, 256>>>(cnt, n);
    k_count<<<eb, 256>>>(edst, cnt, E);
    k_f2h<<<(n * 32 + 255) / 256, 256>>>(x, xh, n * 32);
    k_scan<<<1, 1024>>>(cnt, off, cur, dinv, n);
    k_fill<<<eb, 256>>>(esrc, edst, dinv, cur, epack, E);
    k_wcat<<<(128 * 128 + 255) / 256, 256>>>(Wmu, Wls, bmu, bls, Wcat, bcat);

    // aggregation commutes with the dense projection: agg(x@W) == agg(x)@W.
    // encoder layer 1: h = relu(agg(x)@W1 + b1) -> written as half
    k_agg128h<<<1024, 256>>>(xh, off, epack, dinv, bufA, n);
    k_gemm<128, 1><<<gb, 256>>>(bufA, W1, b1, (float*)hh, nullptr, n);

    // mu / logvar: aggH = agg(h); [mu|lv] = aggH@Wcat + bcat (split epilogue)
    k_agg128h<<<1024, 256>>>(hh, off, epack, dinv, bufA, n);
    k_gemm<128, 2><<<gb, 256>>>(bufA, Wcat, bcat, o_mu, o_lv, n);

    // reparameterize + label head (z @ W_lc + b_lc), fused
    k_z_label<<<1024, 256>>>(eps, o_mu, o_lv, Wlc, blc, o_z, o_label, n);

    // aggZ = agg(z) [64-wide, fp32], shared by recon and gender; gender+gumbel fused
    k_agg64_gumbel<<<1024, 256>>>(o_z, off, epack, dinv, Wg, bg, u, bufA, o_gender, n);

    // recon_x = aggZ @ W_dx + b_dx
    k_gemm<64, 0><<<gb, 256>>>(bufA, Wdx, bdx, o_recon, nullptr, n);
}

// round 16
// speedup vs baseline: 1.3574x; 1.0804x over previous
#include <cuda_runtime.h>
#include <cuda_fp16.h>
#include <math.h>

#define NMAX 50000
#define EMAX 1600000
#define NBMAX 64   // ceil(NMAX/1024) = 49

// ---- static device scratch (no runtime allocation allowed) ----
__device__ int    g_cnt[NMAX];
__device__ int    g_off[NMAX + 1];
__device__ int    g_cur[NMAX];
__device__ int    g_bsum[NBMAX];
__device__ float  g_dinv[NMAX];
__device__ int2   g_epack[EMAX];                    // {src, weight-bits}
__device__ float  g_bufA[(size_t)NMAX * 128];
__device__ __half g_xh[(size_t)NMAX * 128];
__device__ __half g_hh[(size_t)NMAX * 128];
__device__ float  g_Wcat[128 * 128];
__device__ float  g_bcat[128];

// ---------------------------------------------------------------
__global__ void k_zero(int* p, int n) {
    int i = blockIdx.x * blockDim.x + threadIdx.x;
    if (i < n) p[i] = 0;
}

__global__ void k_count(const int* __restrict__ dst, int* __restrict__ cnt, int E) {
    int e = blockIdx.x * blockDim.x + threadIdx.x;
    if (e < E) atomicAdd(&cnt[dst[e]], 1);
}

// phase A: per-1024-tile reduction of cnt -> bsum[tile]
__global__ void k_bsum(const int* __restrict__ cnt, int* __restrict__ bsum, int n) {
    __shared__ int wsum[32];
    int i = blockIdx.x * 1024 + threadIdx.x;
    int lane = threadIdx.x & 31;
    int warp = threadIdx.x >> 5;
    int v = (i < n) ? cnt[i] : 0;
#pragma unroll
    for (int o = 16; o; o >>= 1) v += __shfl_xor_sync(0xFFFFFFFFu, v, o);
    if (lane == 0) wsum[warp] = v;
    __syncthreads();
    if (warp == 0) {
        int y = wsum[lane];
#pragma unroll
        for (int o = 16; o; o >>= 1) y += __shfl_xor_sync(0xFFFFFFFFu, y, o);
        if (lane == 0) bsum[blockIdx.x] = y;
    }
}

// phase B: exclusive scan of nb (<=64) tile sums in-place; writes off[n]=total
__global__ void k_bscan(int* __restrict__ bsum, int* __restrict__ off, int nb, int n) {
    __shared__ int wtot[2];
    int tid = threadIdx.x;           // 64 threads
    int lane = tid & 31;
    int warp = tid >> 5;
    int v = (tid < nb) ? bsum[tid] : 0;
    int x = v;
#pragma unroll
    for (int o = 1; o < 32; o <<= 1) {
        int t = __shfl_up_sync(0xFFFFFFFFu, x, o);
        if (lane >= o) x += t;
    }
    if (lane == 31) wtot[warp] = x;
    __syncthreads();
    int pre = (warp == 1) ? wtot[0] : 0;
    int incl = x + pre;
    if (tid < nb) bsum[tid] = incl - v;     // exclusive
    if (tid == nb - 1) off[n] = incl;       // grand total
}

// phase C: intra-tile shuffle scan + tile offset; writes off/cur/dinv
__global__ void k_scan_final(const int* __restrict__ cnt, const int* __restrict__ bsum,
                             int* __restrict__ off, int* __restrict__ cur,
                             float* __restrict__ dinv, int n) {
    __shared__ int wsum[32];
    int i = blockIdx.x * 1024 + threadIdx.x;
    int lane = threadIdx.x & 31;
    int warp = threadIdx.x >> 5;
    int v = (i < n) ? cnt[i] : 0;
    int x = v;
#pragma unroll
    for (int o = 1; o < 32; o <<= 1) {
        int t = __shfl_up_sync(0xFFFFFFFFu, x, o);
        if (lane >= o) x += t;
    }
    if (lane == 31) wsum[warp] = x;
    __syncthreads();
    if (warp == 0) {
        int y = wsum[lane];
#pragma unroll
        for (int o = 1; o < 32; o <<= 1) {
            int t = __shfl_up_sync(0xFFFFFFFFu, y, o);
            if (lane >= o) y += t;
        }
        wsum[lane] = y;
    }
    __syncthreads();
    int wpre = (warp == 0) ? 0 : wsum[warp - 1];
    if (i < n) {
        int o = bsum[blockIdx.x] + wpre + x - v;   // exclusive prefix
        off[i] = o;
        cur[i] = o;
        dinv[i] = rsqrtf((float)(v + 1));          // self-loop => deg >= 1
    }
}

// fill CSR with packed (src, weight) in one 8B store per edge
__global__ void k_fill(const int* __restrict__ src, const int* __restrict__ dst,
                       const float* __restrict__ dinv, int* __restrict__ cur,
                       int2* __restrict__ epack, int E) {
    int e = blockIdx.x * blockDim.x + threadIdx.x;
    if (e >= E) return;
    int s = src[e], d = dst[e];
    int p = atomicAdd(&cur[d], 1);
    epack[p] = make_int2(s, __float_as_int(dinv[s] * dinv[d]));
}

__global__ void k_wcat(const float* __restrict__ Wmu, const float* __restrict__ Wls,
                       const float* __restrict__ bmu, const float* __restrict__ bls,
                       float* __restrict__ Wcat, float* __restrict__ bcat) {
    int i = blockIdx.x * blockDim.x + threadIdx.x;
    if (i < 128 * 128) {
        int k = i >> 7, p = i & 127;
        Wcat[i] = (p < 64) ? Wmu[k * 64 + p] : Wls[k * 64 + (p - 64)];
    }
    if (i < 128) bcat[i] = (i < 64) ? bmu[i] : bls[i - 64];
}

// fp32 -> fp16 conversion (4 elems/thread)
__global__ void k_f2h(const float* __restrict__ in, __half* __restrict__ out, int total4) {
    int i = blockIdx.x * blockDim.x + threadIdx.x;
    if (i >= total4) return;
    float4 v = __ldg((const float4*)in + i);
    union { __half2 h[2]; uint2 u; } pk;
    pk.h[0] = __floats2half2_rn(v.x, v.y);
    pk.h[1] = __floats2half2_rn(v.z, v.w);
    ((uint2*)out)[i] = pk.u;
}

// load 4 halves (8B) -> float4
__device__ __forceinline__ float4 ldh4(const __half* p) {
    uint2 r = __ldg((const uint2*)p);
    __half2 h0 = *reinterpret_cast<__half2*>(&r.x);
    __half2 h1 = *reinterpret_cast<__half2*>(&r.y);
    float2 f0 = __half22float2(h0);
    float2 f1 = __half22float2(h1);
    return make_float4(f0.x, f0.y, f1.x, f1.y);
}

// C[n x 128] = A[n x K] * W[K x 128] + bias, fp32 SIMT, BM=64, BK=16, 256 threads
// EPI 0: C = acc + bias  (fp32)
// EPI 1: C = relu(acc + bias) written as __half (C reinterpreted)
// EPI 2: split: col<64 -> C[row*64+col], col>=64 -> C2[row*64+col-64]  (both + bias)
template <int K, int EPI>
__global__ void k_gemm(const float* __restrict__ A, const float* __restrict__ W,
                       const float* __restrict__ bias,
                       float* __restrict__ C, float* __restrict__ C2, int n) {
    __shared__ float As[16][64];
    __shared__ float Ws[16][128];
    int tid = threadIdx.x;
    int blockRow = blockIdx.x * 64;
    int ty = tid >> 5;            // 0..7  (uniform per warp)
    int col4 = (tid & 31) * 4;    // 0..124
    float acc[8][4];
#pragma unroll
    for (int r = 0; r < 8; r++)
#pragma unroll
        for (int c = 0; c < 4; c++) acc[r][c] = 0.f;

    for (int k0 = 0; k0 < K; k0 += 16) {
        int rl = tid >> 2;
        int kk4 = (tid & 3) * 4;
        int row = blockRow + rl;
        float4 av = make_float4(0.f, 0.f, 0.f, 0.f);
        if (row < n) av = *(const float4*)(A + (size_t)row * K + k0 + kk4);
        As[kk4 + 0][rl] = av.x;
        As[kk4 + 1][rl] = av.y;
        As[kk4 + 2][rl] = av.z;
        As[kk4 + 3][rl] = av.w;
        int kw = tid >> 4;
        int c8 = (tid & 15) * 8;
        float4 w0 = *(const float4*)(W + (size_t)(k0 + kw) * 128 + c8);
        float4 w1 = *(const float4*)(W + (size_t)(k0 + kw) * 128 + c8 + 4);
        *(float4*)&Ws[kw][c8] = w0;
        *(float4*)&Ws[kw][c8 + 4] = w1;
        __syncthreads();
#pragma unroll
        for (int kk = 0; kk < 16; kk++) {
            float4 wv = *(const float4*)&Ws[kk][col4];
#pragma unroll
            for (int r = 0; r < 8; r++) {
                float a = As[kk][ty * 8 + r];
                acc[r][0] += a * wv.x;
                acc[r][1] += a * wv.y;
                acc[r][2] += a * wv.z;
                acc[r][3] += a * wv.w;
            }
        }
        __syncthreads();
    }
    float4 bv = *(const float4*)(bias + col4);
#pragma unroll
    for (int r = 0; r < 8; r++) {
        int row = blockRow + ty * 8 + r;
        if (row >= n) continue;
        float4 res = make_float4(acc[r][0] + bv.x, acc[r][1] + bv.y,
                                 acc[r][2] + bv.z, acc[r][3] + bv.w);
        if (EPI == 1) {
            res.x = fmaxf(res.x, 0.f); res.y = fmaxf(res.y, 0.f);
            res.z = fmaxf(res.z, 0.f); res.w = fmaxf(res.w, 0.f);
            union { __half2 h[2]; uint2 u; } pk;
            pk.h[0] = __floats2half2_rn(res.x, res.y);
            pk.h[1] = __floats2half2_rn(res.z, res.w);
            __half* Ch = reinterpret_cast<__half*>(C);
            *(uint2*)(Ch + (size_t)row * 128 + col4) = pk.u;
        } else if (EPI == 2) {
            if (col4 < 64)
                *(float4*)(C + (size_t)row * 64 + col4) = res;
            else
                *(float4*)(C2 + (size_t)row * 64 + col4 - 64) = res;
        } else {
            *(float4*)(C + (size_t)row * 128 + col4) = res;
        }
    }
}

// warp-per-node CSR aggregation, 128-wide HALF features, fp32 accum/output:
// out[v] = sum_{e in in(v)} w_e * feat[src_e] + dinv[v]^2 * feat[v]
__global__ void k_agg128h(const __half* __restrict__ feat, const int* __restrict__ off,
                          const int2* __restrict__ ep, const float* __restrict__ dinv,
                          float* __restrict__ out, int n) {
    int gw = (blockIdx.x * blockDim.x + threadIdx.x) >> 5;
    int lane = threadIdx.x & 31;
    int nw = (gridDim.x * blockDim.x) >> 5;
    for (int v = gw; v < n; v += nw) {
        float dv = dinv[v];
        float sw = dv * dv;
        float4 a = ldh4(feat + (size_t)v * 128 + lane * 4);
        float ax = sw * a.x, ay = sw * a.y, az = sw * a.z, aw = sw * a.w;
        int e = off[v], t = off[v + 1];
        for (; e + 3 < t; e += 4) {
            int2 e0 = __ldg(ep + e);
            int2 e1 = __ldg(ep + e + 1);
            int2 e2 = __ldg(ep + e + 2);
            int2 e3 = __ldg(ep + e + 3);
            float4 g0 = ldh4(feat + (size_t)e0.x * 128 + lane * 4);
            float4 g1 = ldh4(feat + (size_t)e1.x * 128 + lane * 4);
            float4 g2 = ldh4(feat + (size_t)e2.x * 128 + lane * 4);
            float4 g3 = ldh4(feat + (size_t)e3.x * 128 + lane * 4);
            float w0 = __int_as_float(e0.y);
            float w1 = __int_as_float(e1.y);
            float w2 = __int_as_float(e2.y);
            float w3 = __int_as_float(e3.y);
            ax += w0 * g0.x + w1 * g1.x + w2 * g2.x + w3 * g3.x;
            ay += w0 * g0.y + w1 * g1.y + w2 * g2.y + w3 * g3.y;
            az += w0 * g0.z + w1 * g1.z + w2 * g2.z + w3 * g3.z;
            aw += w0 * g0.w + w1 * g1.w + w2 * g2.w + w3 * g3.w;
        }
        for (; e < t; e++) {
            int2 e0 = __ldg(ep + e);
            float4 g0 = ldh4(feat + (size_t)e0.x * 128 + lane * 4);
            float w0 = __int_as_float(e0.y);
            ax += w0 * g0.x;
            ay += w0 * g0.y;
            az += w0 * g0.z;
            aw += w0 * g0.w;
        }
        *(float4*)(out + (size_t)v * 128 + lane * 4) = make_float4(ax, ay, az, aw);
    }
}

// fused reparameterize + label classifier (warp-per-node; lane owns cols 2l, 2l+1)
// z = eps * exp(0.5*logvar) + mu ; label = z @ W_lc + b_lc
__global__ void k_z_label(const float* __restrict__ eps, const float* __restrict__ mu,
                          const float* __restrict__ lv, const float* __restrict__ Wlc,
                          const float* __restrict__ blc, float* __restrict__ z,
                          float* __restrict__ out_label, int n) {
    int gw = (blockIdx.x * blockDim.x + threadIdx.x) >> 5;
    int lane = threadIdx.x & 31;
    int nw = (gridDim.x * blockDim.x) >> 5;
    float wl0 = __ldg(Wlc + 2 * lane);
    float wl1 = __ldg(Wlc + 2 * lane + 1);
    float bl = __ldg(blc);
    for (int v = gw; v < n; v += nw) {
        float2 m = *(const float2*)(mu + (size_t)v * 64 + 2 * lane);
        float2 lg = *(const float2*)(lv + (size_t)v * 64 + 2 * lane);
        float2 ee = *(const float2*)(eps + (size_t)v * 64 + 2 * lane);
        float z0 = ee.x * expf(0.5f * lg.x) + m.x;
        float z1 = ee.y * expf(0.5f * lg.y) + m.y;
        *(float2*)(z + (size_t)v * 64 + 2 * lane) = make_float2(z0, z1);
        float l = z0 * wl0 + z1 * wl1;
#pragma unroll
        for (int o = 16; o; o >>= 1) l += __shfl_xor_sync(0xFFFFFFFFu, l, o);
        if (lane == 0) out_label[v] = l + bl;
    }
}

// 64-wide fp32 aggregation of z (shared by recon GEMM and gender head) with fused
// gender logits + Gumbel-softmax epilogue. Lane owns cols 2l, 2l+1 (float2).
// Kept fp32: Gumbel argmax near-ties are sensitive to logit noise.
__global__ void k_agg64_gumbel(const float* __restrict__ z, const int* __restrict__ off,
                               const int2* __restrict__ ep, const float* __restrict__ dinv,
                               const float* __restrict__ Wg, const float* __restrict__ bg,
                               const float* __restrict__ uu,
                               float* __restrict__ aggz, float* __restrict__ out_g, int n) {
    int gw = (blockIdx.x * blockDim.x + threadIdx.x) >> 5;
    int lane = threadIdx.x & 31;
    int nw = (gridDim.x * blockDim.x) >> 5;
    float wg0a = __ldg(Wg + (2 * lane) * 2);
    float wg0b = __ldg(Wg + (2 * lane) * 2 + 1);
    float wg1a = __ldg(Wg + (2 * lane + 1) * 2);
    float wg1b = __ldg(Wg + (2 * lane + 1) * 2 + 1);
    for (int v = gw; v < n; v += nw) {
        float dv = dinv[v];
        float sw = dv * dv;
        float2 a = __ldg((const float2*)(z + (size_t)v * 64) + lane);
        float ax = sw * a.x, ay = sw * a.y;
        int e = off[v], t = off[v + 1];
        for (; e + 3 < t; e += 4) {
            int2 e0 = __ldg(ep + e);
            int2 e1 = __ldg(ep + e + 1);
            int2 e2 = __ldg(ep + e + 2);
            int2 e3 = __ldg(ep + e + 3);
            float2 g0 = __ldg((const float2*)(z + (size_t)e0.x * 64) + lane);
            float2 g1 = __ldg((const float2*)(z + (size_t)e1.x * 64) + lane);
            float2 g2 = __ldg((const float2*)(z + (size_t)e2.x * 64) + lane);
            float2 g3 = __ldg((const float2*)(z + (size_t)e3.x * 64) + lane);
            float w0 = __int_as_float(e0.y);
            float w1 = __int_as_float(e1.y);
            float w2 = __int_as_float(e2.y);
            float w3 = __int_as_float(e3.y);
            ax += w0 * g0.x + w1 * g1.x + w2 * g2.x + w3 * g3.x;
            ay += w0 * g0.y + w1 * g1.y + w2 * g2.y + w3 * g3.y;
        }
        for (; e < t; e++) {
            int2 e0 = __ldg(ep + e);
            float2 g0 = __ldg((const float2*)(z + (size_t)e0.x * 64) + lane);
            float w0 = __int_as_float(e0.y);
            ax += w0 * g0.x;
            ay += w0 * g0.y;
        }
        *(float2*)(aggz + (size_t)v * 64 + 2 * lane) = make_float2(ax, ay);
        // gender logits: aggz @ W_g
        float g0 = ax * wg0a + ay * wg1a;
        float g1 = ax * wg0b + ay * wg1b;
#pragma unroll
        for (int o = 16; o; o >>= 1) {
            g0 += __shfl_xor_sync(0xFFFFFFFFu, g0, o);
            g1 += __shfl_xor_sync(0xFFFFFFFFu, g1, o);
        }
        if (lane == 0) {
            float l0 = g0 + bg[0], l1 = g1 + bg[1];
            float u0 = uu[(size_t)v * 2], u1 = uu[(size_t)v * 2 + 1];
            float gn0 = -logf(-logf(u0 + 1e-20f) + 1e-20f);
            float gn1 = -logf(-logf(u1 + 1e-20f) + 1e-20f);
            float s0 = l0 + gn0, s1 = l1 + gn1;
            float m = fmaxf(s0, s1);
            float e0 = expf(s0 - m), e1 = expf(s1 - m);
            float inv = 1.f / (e0 + e1);
            float y0 = e0 * inv, y1 = e1 * inv;
            float h0 = (s1 > s0) ? 0.f : 1.f;   // argmax; tie -> index 0
            float h1 = 1.f - h0;
            out_g[(size_t)v * 2] = (h0 - y0) + y0;
            out_g[(size_t)v * 2 + 1] = (h1 - y1) + y1;
        }
    }
}

// ---------------------------------------------------------------
extern "C" void kernel_launch(void* const* d_in, const int* in_sizes, int n_in,
                              void* d_out, int out_size) {
    const float* x   = (const float*)d_in[0];
    const int*   ei  = (const int*)d_in[1];
    const float* eps = (const float*)d_in[2];
    const float* u   = (const float*)d_in[3];
    const float* W1  = (const float*)d_in[4];
    const float* b1  = (const float*)d_in[5];
    const float* Wmu = (const float*)d_in[6];
    const float* bmu = (const float*)d_in[7];
    const float* Wls = (const float*)d_in[8];
    const float* bls = (const float*)d_in[9];
    const float* Wdx = (const float*)d_in[10];
    const float* bdx = (const float*)d_in[11];
    const float* Wg  = (const float*)d_in[12];
    const float* bg  = (const float*)d_in[13];
    const float* Wlc = (const float*)d_in[14];
    const float* blc = (const float*)d_in[15];

    int n = in_sizes[0] / 128;     // 50000
    int E = in_sizes[1] / 2;       // 1.6M
    const int* esrc = ei;
    const int* edst = ei + E;

    float* out = (float*)d_out;
    size_t nn = (size_t)n;
    float* o_recon  = out;
    float* o_gender = out + nn * 128;
    float* o_label  = out + nn * 130;
    float* o_mu     = out + nn * 131;
    float* o_lv     = out + nn * 195;
    float* o_z      = out + nn * 259;

    int *cnt, *off, *cur, *bsum;
    int2* epack;
    float *dinv, *bufA, *Wcat, *bcat;
    __half *xh, *hh;
    cudaGetSymbolAddress((void**)&cnt, g_cnt);
    cudaGetSymbolAddress((void**)&off, g_off);
    cudaGetSymbolAddress((void**)&cur, g_cur);
    cudaGetSymbolAddress((void**)&bsum, g_bsum);
    cudaGetSymbolAddress((void**)&dinv, g_dinv);
    cudaGetSymbolAddress((void**)&epack, g_epack);
    cudaGetSymbolAddress((void**)&bufA, g_bufA);
    cudaGetSymbolAddress((void**)&xh, g_xh);
    cudaGetSymbolAddress((void**)&hh, g_hh);
    cudaGetSymbolAddress((void**)&Wcat, g_Wcat);
    cudaGetSymbolAddress((void**)&bcat, g_bcat);

    int eb = (E + 255) / 256;
    int gb = (n + 63) / 64;
    int nb = (n + 1023) / 1024;    // 49 tiles

    // CSR build (dst-grouped, packed) + dinv; convert x to half for gathering
    k_zero<<<(n + 255) / 256, 256>>>(cnt, n);
    k_count<<<eb, 256>>>(edst, cnt, E);
    k_f2h<<<(n * 32 + 255) / 256, 256>>>(x, xh, n * 32);
    // three-phase multi-block exclusive scan (replaces 49.7us single-block scan)
    k_bsum<<<nb, 1024>>>(cnt, bsum, n);
    k_bscan<<<1, 64>>>(bsum, off, nb, n);
    k_scan_final<<<nb, 1024>>>(cnt, bsum, off, cur, dinv, n);
    k_fill<<<eb, 256>>>(esrc, edst, dinv, cur, epack, E);
    k_wcat<<<(128 * 128 + 255) / 256, 256>>>(Wmu, Wls, bmu, bls, Wcat, bcat);

    // aggregation commutes with the dense projection: agg(x@W) == agg(x)@W.
    // encoder layer 1: h = relu(agg(x)@W1 + b1) -> written as half
    k_agg128h<<<1024, 256>>>(xh, off, epack, dinv, bufA, n);
    k_gemm<128, 1><<<gb, 256>>>(bufA, W1, b1, (float*)hh, nullptr, n);

    // mu / logvar: aggH = agg(h); [mu|lv] = aggH@Wcat + bcat (split epilogue)
    k_agg128h<<<1024, 256>>>(hh, off, epack, dinv, bufA, n);
    k_gemm<128, 2><<<gb, 256>>>(bufA, Wcat, bcat, o_mu, o_lv, n);

    // reparameterize + label head (z @ W_lc + b_lc), fused
    k_z_label<<<1024, 256>>>(eps, o_mu, o_lv, Wlc, blc, o_z, o_label, n);

    // aggZ = agg(z) [64-wide, fp32], shared by recon and gender; gender+gumbel fused
    k_agg64_gumbel<<<1024, 256>>>(o_z, off, epack, dinv, Wg, bg, u, bufA, o_gender, n);

    // recon_x = aggZ @ W_dx + b_dx
    k_gemm<64, 0><<<gb, 256>>>(bufA, Wdx, bdx, o_recon, nullptr, n);
}